// round 4
// baseline (speedup 1.0000x reference)
#include <cuda_runtime.h>
#include <math.h>
#include <cstdint>

#define BB 2
#define NN 10000
#define EE 100000
#define HH 128
#define DINN 8
#define DBB 16
#define LL 2
#define NBB 3
#define ROWS_TOT (BB*NN)

// -------- scratch (device globals; no allocation anywhere) --------
__device__ float g_h[ROWS_TOT*HH];
__device__ float g_msum[ROWS_TOT*HH];
__device__ float g_Ga[ROWS_TOT*HH];
__device__ float g_Gb[ROWS_TOT*HH];
__device__ float g_p[ROWS_TOT*3];
__device__ float g_pd[ROWS_TOT*3];
__device__ float g_invdeg[NBB*NN];

// interleaved weight pairs: Wp_u64[k2*128 + j] = (W[2*k2][j], W[2*k2+1][j])
// slots (each 4096 ulonglong2 = 8192 u64):
//  0..5  : msg_W1 rows [0:128)    per lk   (W1a)
//  6..11 : msg_W1 rows [128:256)  per lk   (W1b)
// 12..17 : msg_W2 per lk
// 18..23 : pos_W1 per lk
// 24..25 : upd_W1 rows [0:128)  per l
// 26..27 : upd_W1 rows [128:256) per l
// 28..29 : upd_W2 per l
#define SLOT_ULL2 4096
__device__ ulonglong2 g_Wp[30*SLOT_ULL2];

__device__ __forceinline__ float siluf(float x){ return x / (1.0f + __expf(-x)); }

__device__ __forceinline__ void ffma2(unsigned long long& c,
                                      unsigned long long a,
                                      unsigned long long b){
  asm("fma.rn.f32x2 %0, %1, %2, %0;" : "+l"(c) : "l"(a), "l"(b));
}
__device__ __forceinline__ float pairsum(unsigned long long v){
  return __uint_as_float((unsigned)v) + __uint_as_float((unsigned)(v>>32));
}
__device__ __forceinline__ unsigned long long fpack(float lo, float hi){
  return (unsigned long long)__float_as_uint(lo)
       | ((unsigned long long)__float_as_uint(hi) << 32);
}

// ------------------- weight interleaving setup -------------------
__global__ void k_interleave(const float* __restrict__ mW1, const float* __restrict__ mW2,
                             const float* __restrict__ pW1, const float* __restrict__ uW1,
                             const float* __restrict__ uW2){
  int gi = blockIdx.x*blockDim.x + threadIdx.x;   // over 30*8192 u64 elements
  if (gi >= 30*8192) return;
  int slot = gi >> 13;
  int e    = gi & 8191;
  int k2 = e >> 7, j = e & 127;
  const float* src;
  if      (slot < 6)   src = mW1 + (size_t)slot*257*HH;                 // W1a
  else if (slot < 12)  src = mW1 + (size_t)(slot-6)*257*HH + 128*HH;    // W1b
  else if (slot < 18)  src = mW2 + (size_t)(slot-12)*HH*HH;
  else if (slot < 24)  src = pW1 + (size_t)(slot-18)*HH*HH;
  else if (slot < 26)  src = uW1 + (size_t)(slot-24)*2*HH*HH;           // uW1a
  else if (slot < 28)  src = uW1 + (size_t)(slot-26)*2*HH*HH + HH*HH;   // uW1b
  else                 src = uW2 + (size_t)(slot-28)*HH*HH;
  float lo = src[(size_t)(2*k2)*HH + j];
  float hi = src[(size_t)(2*k2+1)*HH + j];
  ((unsigned long long*)g_Wp)[(size_t)slot*8192 + e] = fpack(lo, hi);
}

// ------------------- small setup kernels -------------------
__global__ void k_deg_zero(){
  int i = blockIdx.x*blockDim.x + threadIdx.x;
  if(i < NBB*NN) g_invdeg[i] = 0.f;
}
__global__ void k_deg_count(const int* __restrict__ edst){
  int i = blockIdx.x*blockDim.x + threadIdx.x;
  if(i < NBB*EE){
    int k = i / EE;
    atomicAdd(&g_invdeg[k*NN + edst[i]], 1.f);
  }
}
__global__ void k_deg_fin(){
  int i = blockIdx.x*blockDim.x + threadIdx.x;
  if(i < NBB*NN) g_invdeg[i] = 1.f / fmaxf(g_invdeg[i], 1.f);
}

__global__ void k_init_h(const float* __restrict__ base, const float* __restrict__ Win,
                         const float* __restrict__ b_in){
  int n = blockIdx.x, j = threadIdx.x;
  float acc = b_in[j];
  #pragma unroll
  for(int d=0; d<DBB; d++)
    acc = fmaf(__ldg(&base[n*DBB+d]), __ldg(&Win[d*HH+j]), acc);
  g_h[n*HH+j] = acc;
  g_h[(NN+n)*HH+j] = acc;
}

__global__ void k_add_dyn(const float* __restrict__ x, const float* __restrict__ Win,
                          const int* __restrict__ ent){
  int t = threadIdx.x;
  if(t < BB*HH){
    int b = t >> 7, j = t & (HH-1);
    float acc = 0.f;
    #pragma unroll
    for(int d=0; d<DINN; d++)
      acc = fmaf(x[b*DINN+d], Win[(DBB+d)*HH+j], acc);
    g_h[((size_t)b*NN + ent[b])*HH + j] += acc;
  }
}

__global__ void k_init_p(const float* __restrict__ bp){
  int i = blockIdx.x*blockDim.x + threadIdx.x;
  if(i < NN*3){ float v = bp[i]; g_p[i] = v; g_p[NN*3+i] = v; }
}

__global__ void k_zero_layer(){
  int i = blockIdx.x*blockDim.x + threadIdx.x;
  if(i < ROWS_TOT*HH) g_msum[i] = 0.f;
  if(i < ROWS_TOT*3)  g_pd[i]   = 0.f;
}

__global__ void k_padd(){
  int i = blockIdx.x*blockDim.x + threadIdx.x;
  if(i < ROWS_TOT*3) g_p[i] += g_pd[i];
}

// ------------------- FFMA2 register-tiled 64x128 (K=128) micro-GEMM -------------------
// sA: smem activations [64][132] (k-contiguous rows); Wp: interleaved pair weights
// (ulonglong2, 64 per k2-row). Thread computes 4 rows x 8 cols; accumulators are
// f32x2 pairs (even-k partial lo, odd-k partial hi).
__device__ __forceinline__ void gemm_128_x2(const float* __restrict__ sA, int r0,
                                            const ulonglong2* __restrict__ Wp, int j0,
                                            unsigned long long acc[4][8]){
  const ulonglong2* wrow = Wp + (j0 >> 1);
  #pragma unroll 4
  for(int k2=0; k2<64; k2++){
    ulonglong2 w01 = __ldg(wrow + 0);
    ulonglong2 w23 = __ldg(wrow + 1);
    ulonglong2 w45 = __ldg(wrow + 2);
    ulonglong2 w67 = __ldg(wrow + 3);
    wrow += 64;
    unsigned long long a[4];
    #pragma unroll
    for(int i=0;i<4;i++)
      a[i] = *(const unsigned long long*)(sA + (r0+i)*132 + k2*2);
    #pragma unroll
    for(int i=0;i<4;i++){
      ffma2(acc[i][0], a[i], w01.x);
      ffma2(acc[i][1], a[i], w01.y);
      ffma2(acc[i][2], a[i], w23.x);
      ffma2(acc[i][3], a[i], w23.y);
      ffma2(acc[i][4], a[i], w45.x);
      ffma2(acc[i][5], a[i], w45.y);
      ffma2(acc[i][6], a[i], w67.x);
      ffma2(acc[i][7], a[i], w67.y);
    }
  }
}

// ------------------- node precompute: Ga = h@W1a, Gb = h@W1b -------------------
__global__ void __launch_bounds__(256,2) k_gagb(int lk){
  __shared__ float sA[64*132];
  int tid = threadIdx.x;
  int base = blockIdx.x*64;
  int c4 = tid & 31, rs = tid >> 5;
  int tx = tid & 15, ty = tid >> 4;
  int r0 = ty*4, j0 = tx*8;

  #pragma unroll
  for(int it=0; it<8; it++){
    int r = it*8 + rs;
    int rg = base + r;
    float4 v = make_float4(0.f,0.f,0.f,0.f);
    if(rg < ROWS_TOT) v = __ldg((const float4*)(g_h + (size_t)rg*HH) + c4);
    *(float4*)(sA + r*132 + c4*4) = v;
  }
  __syncthreads();

  for(int half=0; half<2; half++){
    const ulonglong2* Wp = g_Wp + (size_t)(half*6 + lk)*SLOT_ULL2;
    unsigned long long acc[4][8];
    #pragma unroll
    for(int i=0;i<4;i++)
      #pragma unroll
      for(int j=0;j<8;j++) acc[i][j]=0ull;
    gemm_128_x2(sA, r0, Wp, j0, acc);
    float* out = half ? g_Gb : g_Ga;
    #pragma unroll
    for(int i=0;i<4;i++){
      int rg = base + r0 + i;
      if(rg < ROWS_TOT){
        float4 o0 = make_float4(pairsum(acc[i][0]),pairsum(acc[i][1]),
                                pairsum(acc[i][2]),pairsum(acc[i][3]));
        float4 o1 = make_float4(pairsum(acc[i][4]),pairsum(acc[i][5]),
                                pairsum(acc[i][6]),pairsum(acc[i][7]));
        *(float4*)(out + (size_t)rg*HH + j0)     = o0;
        *(float4*)(out + (size_t)rg*HH + j0 + 4) = o1;
      }
    }
  }
}

// ------------------- fused edge kernel (per l,k): 64 edge-rows / block -------------------
__global__ void __launch_bounds__(256,2) k_edge(
    const float* __restrict__ W1r, const float* __restrict__ b1,
    const float* __restrict__ b2,
    const float* __restrict__ pb1,
    const float* __restrict__ pW2, const float* __restrict__ pb2,
    const int* __restrict__ esrc,  const int* __restrict__ edst,
    int lk, int kdeg){
  __shared__ float sM[64*132];
  __shared__ int   sDstRow[64];
  __shared__ int   sSrcRow[64];
  __shared__ float sInv[64];
  __shared__ float sD2[64];
  __shared__ float sRel[64*3];

  int tid = threadIdx.x;
  int base = blockIdx.x*64;

  if(tid < 64){
    int rg = base + tid;
    int b = rg / EE;
    int e = rg - b*EE;
    int ds = edst[e], sr = esrc[e];
    int drow = b*NN + ds, srow = b*NN + sr;
    float rx = g_p[drow*3+0] - g_p[srow*3+0];
    float ry = g_p[drow*3+1] - g_p[srow*3+1];
    float rz = g_p[drow*3+2] - g_p[srow*3+2];
    sRel[tid*3+0] = rx; sRel[tid*3+1] = ry; sRel[tid*3+2] = rz;
    sD2[tid]  = rx*rx + ry*ry + rz*rz;
    sInv[tid] = g_invdeg[kdeg*NN + ds];
    sDstRow[tid] = drow;
    sSrcRow[tid] = srow;
  }
  __syncthreads();

  // m = silu(Ga[dst] + Gb[src] + d2*W1[256] + b1)
  {
    int c4 = tid & 31, rs = tid >> 5;
    float4 w4 = __ldg((const float4*)W1r + c4);
    float4 bb = __ldg((const float4*)b1  + c4);
    #pragma unroll
    for(int it=0; it<8; it++){
      int r = it*8 + rs;
      float4 ga = __ldg((const float4*)(g_Ga + (size_t)sDstRow[r]*HH) + c4);
      float4 gb = __ldg((const float4*)(g_Gb + (size_t)sSrcRow[r]*HH) + c4);
      float d2 = sD2[r];
      float4 o;
      o.x = siluf(ga.x + gb.x + d2*w4.x + bb.x);
      o.y = siluf(ga.y + gb.y + d2*w4.y + bb.y);
      o.z = siluf(ga.z + gb.z + d2*w4.z + bb.z);
      o.w = siluf(ga.w + gb.w + d2*w4.w + bb.w);
      *(float4*)(sM + r*132 + c4*4) = o;
    }
  }
  __syncthreads();

  int tx = tid & 15, ty = tid >> 4;
  int r0 = ty*4, j0 = tx*8;

  // m2 = silu(m @ W2 + b2)
  unsigned long long acc[4][8];
  #pragma unroll
  for(int i=0;i<4;i++)
    #pragma unroll
    for(int j=0;j<8;j++) acc[i][j]=0ull;
  gemm_128_x2(sM, r0, g_Wp + (size_t)(12+lk)*SLOT_ULL2, j0, acc);

  float bv[8];
  { float4 t0 = __ldg((const float4*)(b2+j0)); float4 t1 = __ldg((const float4*)(b2+j0+4));
    bv[0]=t0.x;bv[1]=t0.y;bv[2]=t0.z;bv[3]=t0.w;bv[4]=t1.x;bv[5]=t1.y;bv[6]=t1.z;bv[7]=t1.w; }

  float m2[4][8];
  #pragma unroll
  for(int i=0;i<4;i++)
    #pragma unroll
    for(int j=0;j<8;j++) m2[i][j] = siluf(pairsum(acc[i][j]) + bv[j]);

  // scatter m_sum += m2 / deg[dst]
  #pragma unroll
  for(int i=0;i<4;i++){
    int row = sDstRow[r0+i];
    float sc = sInv[r0+i];
    float* dst = g_msum + (size_t)row*HH + j0;
    #pragma unroll
    for(int j=0;j<8;j++) atomicAdd(dst+j, m2[i][j]*sc);
  }
  __syncthreads();   // all reads of sM (old m) done
  #pragma unroll
  for(int i=0;i<4;i++){
    *(float4*)(sM + (r0+i)*132 + j0)     = make_float4(m2[i][0],m2[i][1],m2[i][2],m2[i][3]);
    *(float4*)(sM + (r0+i)*132 + j0 + 4) = make_float4(m2[i][4],m2[i][5],m2[i][6],m2[i][7]);
  }
  __syncthreads();

  // c1 = silu(m2 @ pW1 + pb1);  coef = c1 @ pW2 + pb2
  #pragma unroll
  for(int i=0;i<4;i++)
    #pragma unroll
    for(int j=0;j<8;j++) acc[i][j]=0ull;
  gemm_128_x2(sM, r0, g_Wp + (size_t)(18+lk)*SLOT_ULL2, j0, acc);

  { float4 t0 = __ldg((const float4*)(pb1+j0)); float4 t1 = __ldg((const float4*)(pb1+j0+4));
    bv[0]=t0.x;bv[1]=t0.y;bv[2]=t0.z;bv[3]=t0.w;bv[4]=t1.x;bv[5]=t1.y;bv[6]=t1.z;bv[7]=t1.w; }
  float wv2[8];
  { float4 t0 = __ldg((const float4*)(pW2+j0)); float4 t1 = __ldg((const float4*)(pW2+j0+4));
    wv2[0]=t0.x;wv2[1]=t0.y;wv2[2]=t0.z;wv2[3]=t0.w;wv2[4]=t1.x;wv2[5]=t1.y;wv2[6]=t1.z;wv2[7]=t1.w; }

  float part[4];
  #pragma unroll
  for(int i=0;i<4;i++){
    float s = 0.f;
    #pragma unroll
    for(int j=0;j<8;j++) s = fmaf(siluf(pairsum(acc[i][j]) + bv[j]), wv2[j], s);
    part[i] = s;
  }
  #pragma unroll
  for(int off=8; off>=1; off>>=1){
    #pragma unroll
    for(int i=0;i<4;i++) part[i] += __shfl_xor_sync(0xffffffffu, part[i], off);
  }
  if(tx == 0){
    float pb2v = __ldg(pb2);
    #pragma unroll
    for(int i=0;i<4;i++){
      int r = r0 + i;
      float s = (part[i] + pb2v) * sInv[r];
      int row = sDstRow[r];
      atomicAdd(&g_pd[row*3+0], sRel[r*3+0]*s);
      atomicAdd(&g_pd[row*3+1], sRel[r*3+1]*s);
      atomicAdd(&g_pd[row*3+2], sRel[r*3+2]*s);
    }
  }
}

// ------------------- node update: h += MLP([h, m_sum]) -------------------
__global__ void __launch_bounds__(256,2) k_update(
    const float* __restrict__ bu1, const float* __restrict__ bu2, int l){
  __shared__ float sA[64*132];
  int tid = threadIdx.x;
  int base = blockIdx.x*64;
  int c4 = tid & 31, rs = tid >> 5;
  int tx = tid & 15, ty = tid >> 4;
  int r0 = ty*4, j0 = tx*8;

  unsigned long long acc[4][8];
  #pragma unroll
  for(int i=0;i<4;i++)
    #pragma unroll
    for(int j=0;j<8;j++) acc[i][j]=0ull;

  #pragma unroll
  for(int it=0; it<8; it++){
    int r = it*8 + rs;
    int rg = base + r;
    float4 v = make_float4(0.f,0.f,0.f,0.f);
    if(rg < ROWS_TOT) v = __ldg((const float4*)(g_h + (size_t)rg*HH) + c4);
    *(float4*)(sA + r*132 + c4*4) = v;
  }
  __syncthreads();
  gemm_128_x2(sA, r0, g_Wp + (size_t)(24+l)*SLOT_ULL2, j0, acc);
  __syncthreads();
  #pragma unroll
  for(int it=0; it<8; it++){
    int r = it*8 + rs;
    int rg = base + r;
    float4 v = make_float4(0.f,0.f,0.f,0.f);
    if(rg < ROWS_TOT) v = __ldg((const float4*)(g_msum + (size_t)rg*HH) + c4);
    *(float4*)(sA + r*132 + c4*4) = v;
  }
  __syncthreads();
  gemm_128_x2(sA, r0, g_Wp + (size_t)(26+l)*SLOT_ULL2, j0, acc);

  float bv[8];
  { float4 t0 = __ldg((const float4*)(bu1+j0)); float4 t1 = __ldg((const float4*)(bu1+j0+4));
    bv[0]=t0.x;bv[1]=t0.y;bv[2]=t0.z;bv[3]=t0.w;bv[4]=t1.x;bv[5]=t1.y;bv[6]=t1.z;bv[7]=t1.w; }
  float t1v[4][8];
  #pragma unroll
  for(int i=0;i<4;i++)
    #pragma unroll
    for(int j=0;j<8;j++) t1v[i][j] = siluf(pairsum(acc[i][j]) + bv[j]);

  __syncthreads();
  #pragma unroll
  for(int i=0;i<4;i++){
    *(float4*)(sA + (r0+i)*132 + j0)     = make_float4(t1v[i][0],t1v[i][1],t1v[i][2],t1v[i][3]);
    *(float4*)(sA + (r0+i)*132 + j0 + 4) = make_float4(t1v[i][4],t1v[i][5],t1v[i][6],t1v[i][7]);
  }
  __syncthreads();

  #pragma unroll
  for(int i=0;i<4;i++)
    #pragma unroll
    for(int j=0;j<8;j++) acc[i][j]=0ull;
  gemm_128_x2(sA, r0, g_Wp + (size_t)(28+l)*SLOT_ULL2, j0, acc);

  { float4 t0 = __ldg((const float4*)(bu2+j0)); float4 t1 = __ldg((const float4*)(bu2+j0+4));
    bv[0]=t0.x;bv[1]=t0.y;bv[2]=t0.z;bv[3]=t0.w;bv[4]=t1.x;bv[5]=t1.y;bv[6]=t1.z;bv[7]=t1.w; }

  #pragma unroll
  for(int i=0;i<4;i++){
    int rg = base + r0 + i;
    if(rg < ROWS_TOT){
      float* hp = g_h + (size_t)rg*HH + j0;
      float4 h0 = *(float4*)hp;
      float4 h1 = *((float4*)hp + 1);
      h0.x += pairsum(acc[i][0])+bv[0]; h0.y += pairsum(acc[i][1])+bv[1];
      h0.z += pairsum(acc[i][2])+bv[2]; h0.w += pairsum(acc[i][3])+bv[3];
      h1.x += pairsum(acc[i][4])+bv[4]; h1.y += pairsum(acc[i][5])+bv[5];
      h1.z += pairsum(acc[i][6])+bv[6]; h1.w += pairsum(acc[i][7])+bv[7];
      *(float4*)hp = h0;
      *((float4*)hp + 1) = h1;
    }
  }
}

// ------------------- readout -------------------
__global__ void k_readout(const float* __restrict__ W1, const float* __restrict__ b1,
                          const float* __restrict__ W2, const float* __restrict__ b2,
                          const int* __restrict__ ent, float* __restrict__ out){
  __shared__ float se[HH];
  __shared__ float sred[HH];
  int j = threadIdx.x;
  for(int b=0; b<BB; b++){
    int row = b*NN + ent[b];
    se[j] = g_h[(size_t)row*HH + j];
    __syncthreads();
    float acc = b1[j];
    #pragma unroll 4
    for(int i=0;i<HH;i++) acc = fmaf(se[i], W1[i*HH+j], acc);
    sred[j] = siluf(acc) * W2[j];
    __syncthreads();
    for(int s=64; s>0; s>>=1){
      if(j<s) sred[j] += sred[j+s];
      __syncthreads();
    }
    if(j==0) out[b] = sred[0] + b2[0];
    __syncthreads();
  }
}

// ------------------- launch -------------------
extern "C" void kernel_launch(void* const* d_in, const int* in_sizes, int n_in,
                              void* d_out, int out_size){
  (void)in_sizes; (void)n_in; (void)out_size;
  const float* x     = (const float*)d_in[0];
  const float* basef = (const float*)d_in[1];
  const float* basep = (const float*)d_in[2];
  const float* Win   = (const float*)d_in[3];
  const float* b_in  = (const float*)d_in[4];
  const float* mW1   = (const float*)d_in[5];
  const float* mb1   = (const float*)d_in[6];
  const float* mW2   = (const float*)d_in[7];
  const float* mb2   = (const float*)d_in[8];
  const float* pW1   = (const float*)d_in[9];
  const float* pb1   = (const float*)d_in[10];
  const float* pW2   = (const float*)d_in[11];
  const float* pb2   = (const float*)d_in[12];
  const float* uW1   = (const float*)d_in[13];
  const float* ub1   = (const float*)d_in[14];
  const float* uW2   = (const float*)d_in[15];
  const float* ub2   = (const float*)d_in[16];
  const float* oW1   = (const float*)d_in[17];
  const float* ob1   = (const float*)d_in[18];
  const float* oW2   = (const float*)d_in[19];
  const float* ob2   = (const float*)d_in[20];
  const int*   ent   = (const int*)d_in[21];
  const int*   esrc  = (const int*)d_in[22];
  const int*   edst  = (const int*)d_in[23];
  float* out = (float*)d_out;

  k_interleave<<<(30*8192+255)/256, 256>>>(mW1, mW2, pW1, uW1, uW2);

  k_deg_zero <<<(NBB*NN+255)/256, 256>>>();
  k_deg_count<<<(NBB*EE+255)/256, 256>>>(edst);
  k_deg_fin  <<<(NBB*NN+255)/256, 256>>>();

  k_init_h <<<NN, 128>>>(basef, Win, b_in);
  k_add_dyn<<<1, 256>>>(x, Win, ent);
  k_init_p <<<(NN*3+255)/256, 256>>>(basep);

  for(int l=0; l<LL; l++){
    k_zero_layer<<<(ROWS_TOT*HH+255)/256, 256>>>();
    for(int k=0; k<NBB; k++){
      int lk = l*NBB + k;
      const float* W1lk = mW1 + (size_t)lk*257*HH;
      k_gagb<<<(ROWS_TOT+63)/64, 256>>>(lk);
      k_edge<<<(BB*EE)/64, 256>>>(
          W1lk + 256*HH,
          mb1 + (size_t)lk*HH,
          mb2 + (size_t)lk*HH,
          pb1 + (size_t)lk*HH,
          pW2 + (size_t)lk*HH,
          pb2 + lk,
          esrc + (size_t)k*EE,
          edst + (size_t)k*EE,
          lk, k);
    }
    k_update<<<(ROWS_TOT+63)/64, 256>>>(
        ub1 + (size_t)l*HH,
        ub2 + (size_t)l*HH,
        l);
    k_padd<<<(ROWS_TOT*3+255)/256, 256>>>();
  }

  k_readout<<<1, 128>>>(oW1, ob1, oW2, ob2, ent, out);
}

// round 5
// speedup vs baseline: 2.1838x; 2.1838x over previous
#include <cuda_runtime.h>
#include <math.h>

#define BB 2
#define NN 10000
#define EE 100000
#define HH 128
#define DINN 8
#define DBB 16
#define LL 2
#define NBB 3
#define ROWS_TOT (BB*NN)
#define ETILES ((EE+63)/64)
#define DELTA_GRID 1184

// -------- scratch (device globals; no allocation anywhere) --------
__device__ float g_h[ROWS_TOT*HH];      // node features [B*N,H]
__device__ float g_msum[ROWS_TOT*HH];   // message aggregation
__device__ float g_Ga[ROWS_TOT*HH];     // h @ W1[0:128]   (per l,k)
__device__ float g_Gb[ROWS_TOT*HH];     // h @ W1[128:256] (per l,k)
__device__ float g_p[ROWS_TOT*3];       // positions
__device__ float g_pd[ROWS_TOT*3];      // position delta
__device__ float g_invdeg[NBB*NN];      // 1/max(deg,1) per neighborhood
__device__ int   g_dirty[NN];           // nodes where b1 state differs from b0
__device__ int   g_newDirty[NN];
__device__ int   g_acount;
__device__ int   g_alist[EE];

__device__ __forceinline__ float siluf(float x){ return x / (1.0f + __expf(-x)); }

// ------------------- small setup kernels -------------------
__global__ void k_deg_zero(){
  int i = blockIdx.x*blockDim.x + threadIdx.x;
  if(i < NBB*NN) g_invdeg[i] = 0.f;
  if(i < NN) g_dirty[i] = 0;
}
__global__ void k_deg_count(const int* __restrict__ edst){
  int i = blockIdx.x*blockDim.x + threadIdx.x;
  if(i < NBB*EE){
    int k = i / EE;
    atomicAdd(&g_invdeg[k*NN + edst[i]], 1.f);
  }
}
__global__ void k_deg_fin(const int* __restrict__ ent){
  int i = blockIdx.x*blockDim.x + threadIdx.x;
  if(i < NBB*NN) g_invdeg[i] = 1.f / fmaxf(g_invdeg[i], 1.f);
  if(i < BB) g_dirty[ent[i]] = 1;
}

__global__ void k_init_h(const float* __restrict__ base, const float* __restrict__ Win,
                         const float* __restrict__ b_in){
  int n = blockIdx.x, j = threadIdx.x;
  float acc = b_in[j];
  #pragma unroll
  for(int d=0; d<DBB; d++)
    acc = fmaf(__ldg(&base[n*DBB+d]), __ldg(&Win[d*HH+j]), acc);
  g_h[n*HH+j] = acc;
  g_h[(NN+n)*HH+j] = acc;   // base part identical across batch
}

__global__ void k_add_dyn(const float* __restrict__ x, const float* __restrict__ Win,
                          const int* __restrict__ ent){
  int t = threadIdx.x;
  if(t < BB*HH){
    int b = t >> 7, j = t & (HH-1);
    float acc = 0.f;
    #pragma unroll
    for(int d=0; d<DINN; d++)
      acc = fmaf(x[b*DINN+d], Win[(DBB+d)*HH+j], acc);
    g_h[((size_t)b*NN + ent[b])*HH + j] += acc;
  }
}

__global__ void k_init_p(const float* __restrict__ bp){
  int i = blockIdx.x*blockDim.x + threadIdx.x;
  if(i < NN*3){ float v = bp[i]; g_p[i] = v; g_p[NN*3+i] = v; }
}

__global__ void k_zero_layer(){
  int i = blockIdx.x*blockDim.x + threadIdx.x;
  if(i < ROWS_TOT*HH) g_msum[i] = 0.f;
  if(i < ROWS_TOT*3)  g_pd[i]   = 0.f;
  if(i < NN)          g_newDirty[i] = 0;
}

// merge b0 contributions into b1 regions; merge dirty flags
__global__ void k_merge(){
  int i = blockIdx.x*blockDim.x + threadIdx.x;
  if(i < NN*HH) g_msum[(size_t)NN*HH + i] += g_msum[i];
  if(i < NN*3)  g_pd[NN*3 + i] += g_pd[i];
  if(i < NN){ if(g_newDirty[i]) g_dirty[i] = 1; }
}

__global__ void k_padd(){
  int i = blockIdx.x*blockDim.x + threadIdx.x;
  if(i < ROWS_TOT*3) g_p[i] += g_pd[i];
}

__global__ void k_zero_cnt(){ g_acount = 0; }

__global__ void k_buildA(const int* __restrict__ esrc, const int* __restrict__ edst){
  int i = blockIdx.x*blockDim.x + threadIdx.x;
  if(i < EE){
    if(g_dirty[esrc[i]] | g_dirty[edst[i]]){
      int pos = atomicAdd(&g_acount, 1);
      g_alist[pos] = i;
    }
  }
}

// ------------------- register-tiled 64x128 (K=128) micro-GEMM -------------------
__device__ __forceinline__ void gemm_128(const float* __restrict__ sA, int r0,
                                         const float* __restrict__ W, int j0,
                                         float acc[4][8]){
  #pragma unroll 2
  for(int kk=0; kk<HH; kk++){
    float4 w0 = __ldg((const float4*)(W + kk*HH + j0));
    float4 w1 = __ldg((const float4*)(W + kk*HH + j0 + 4));
    float a[4];
    #pragma unroll
    for(int i=0;i<4;i++) a[i] = sA[(r0+i)*132 + kk];
    float w[8] = {w0.x,w0.y,w0.z,w0.w,w1.x,w1.y,w1.z,w1.w};
    #pragma unroll
    for(int i=0;i<4;i++)
      #pragma unroll
      for(int j=0;j<8;j++)
        acc[i][j] = fmaf(a[i], w[j], acc[i][j]);
  }
}

// ------------------- node precompute: Ga = h@W1a, Gb = h@W1b (both batches) -------------------
__global__ void __launch_bounds__(256,2) k_gagb(const float* __restrict__ W1){
  __shared__ float sA[64*132];
  int tid = threadIdx.x;
  int base = blockIdx.x*64;
  int c4 = tid & 31, rs = tid >> 5;
  int tx = tid & 15, ty = tid >> 4;
  int r0 = ty*4, j0 = tx*8;

  #pragma unroll
  for(int it=0; it<8; it++){
    int r = it*8 + rs;
    int rg = base + r;
    float4 v = make_float4(0.f,0.f,0.f,0.f);
    if(rg < ROWS_TOT) v = __ldg((const float4*)(g_h + (size_t)rg*HH) + c4);
    *(float4*)(sA + r*132 + c4*4) = v;
  }
  __syncthreads();

  for(int half=0; half<2; half++){
    const float* Wb = W1 + half*HH*HH;
    float acc[4][8];
    #pragma unroll
    for(int i=0;i<4;i++)
      #pragma unroll
      for(int j=0;j<8;j++) acc[i][j]=0.f;
    gemm_128(sA, r0, Wb, j0, acc);
    float* out = half ? g_Gb : g_Ga;
    #pragma unroll
    for(int i=0;i<4;i++){
      int rg = base + r0 + i;
      if(rg < ROWS_TOT){
        float4 o0 = make_float4(acc[i][0],acc[i][1],acc[i][2],acc[i][3]);
        float4 o1 = make_float4(acc[i][4],acc[i][5],acc[i][6],acc[i][7]);
        *(float4*)(out + (size_t)rg*HH + j0)     = o0;
        *(float4*)(out + (size_t)rg*HH + j0 + 4) = o1;
      }
    }
  }
}

// ------------------- fused edge kernel (batch 0 ONLY): 64 edges / block -------------------
__global__ void __launch_bounds__(256,2) k_edge(
    const float* __restrict__ W1r, const float* __restrict__ b1,
    const float* __restrict__ W2,  const float* __restrict__ b2,
    const float* __restrict__ pW1, const float* __restrict__ pb1,
    const float* __restrict__ pW2, const float* __restrict__ pb2,
    const int* __restrict__ esrc,  const int* __restrict__ edst, int kdeg){
  __shared__ float sM[64*132];
  __shared__ int   sDstRow[64];
  __shared__ int   sSrcRow[64];
  __shared__ float sInv[64];
  __shared__ float sD2[64];
  __shared__ float sRel[64*3];

  int tid = threadIdx.x;
  int base = blockIdx.x*64;

  if(tid < 64){
    int e = base + tid;
    bool v = e < EE;
    int ee = v ? e : 0;
    int ds = edst[ee], sr = esrc[ee];
    float rx = g_p[ds*3+0] - g_p[sr*3+0];
    float ry = g_p[ds*3+1] - g_p[sr*3+1];
    float rz = g_p[ds*3+2] - g_p[sr*3+2];
    sRel[tid*3+0] = rx; sRel[tid*3+1] = ry; sRel[tid*3+2] = rz;
    sD2[tid]  = rx*rx + ry*ry + rz*rz;
    sInv[tid] = v ? g_invdeg[kdeg*NN + ds] : 0.f;   // inv=0 makes tail rows exact no-ops
    sDstRow[tid] = ds;
    sSrcRow[tid] = sr;
  }
  __syncthreads();

  // m = silu(Ga[dst] + Gb[src] + d2*W1[256] + b1)
  {
    int c4 = tid & 31, rs = tid >> 5;
    float4 w4 = __ldg((const float4*)W1r + c4);
    float4 bb = __ldg((const float4*)b1  + c4);
    #pragma unroll
    for(int it=0; it<8; it++){
      int r = it*8 + rs;
      float4 ga = __ldg((const float4*)(g_Ga + (size_t)sDstRow[r]*HH) + c4);
      float4 gb = __ldg((const float4*)(g_Gb + (size_t)sSrcRow[r]*HH) + c4);
      float d2 = sD2[r];
      float4 o;
      o.x = siluf(ga.x + gb.x + d2*w4.x + bb.x);
      o.y = siluf(ga.y + gb.y + d2*w4.y + bb.y);
      o.z = siluf(ga.z + gb.z + d2*w4.z + bb.z);
      o.w = siluf(ga.w + gb.w + d2*w4.w + bb.w);
      *(float4*)(sM + r*132 + c4*4) = o;
    }
  }
  __syncthreads();

  int tx = tid & 15, ty = tid >> 4;
  int r0 = ty*4, j0 = tx*8;

  // m2 = silu(m @ W2 + b2)
  float acc[4][8];
  #pragma unroll
  for(int i=0;i<4;i++)
    #pragma unroll
    for(int j=0;j<8;j++) acc[i][j]=0.f;
  gemm_128(sM, r0, W2, j0, acc);

  float bv[8];
  { float4 t0 = __ldg((const float4*)(b2+j0)); float4 t1 = __ldg((const float4*)(b2+j0+4));
    bv[0]=t0.x;bv[1]=t0.y;bv[2]=t0.z;bv[3]=t0.w;bv[4]=t1.x;bv[5]=t1.y;bv[6]=t1.z;bv[7]=t1.w; }

  float m2[4][8];
  #pragma unroll
  for(int i=0;i<4;i++)
    #pragma unroll
    for(int j=0;j<8;j++) m2[i][j] = siluf(acc[i][j] + bv[j]);

  // scatter m_sum += m2 / deg[dst]   (inv=0 rows add exact +0.0 — harmless)
  #pragma unroll
  for(int i=0;i<4;i++){
    int row = sDstRow[r0+i];
    float sc = sInv[r0+i];
    float* dst = g_msum + (size_t)row*HH + j0;
    #pragma unroll
    for(int j=0;j<8;j++) atomicAdd(dst+j, m2[i][j]*sc);
  }
  __syncthreads();
  #pragma unroll
  for(int i=0;i<4;i++){
    *(float4*)(sM + (r0+i)*132 + j0)     = make_float4(m2[i][0],m2[i][1],m2[i][2],m2[i][3]);
    *(float4*)(sM + (r0+i)*132 + j0 + 4) = make_float4(m2[i][4],m2[i][5],m2[i][6],m2[i][7]);
  }
  __syncthreads();

  // c1 = silu(m2 @ pW1 + pb1);  coef = c1 @ pW2 + pb2
  #pragma unroll
  for(int i=0;i<4;i++)
    #pragma unroll
    for(int j=0;j<8;j++) acc[i][j]=0.f;
  gemm_128(sM, r0, pW1, j0, acc);

  { float4 t0 = __ldg((const float4*)(pb1+j0)); float4 t1 = __ldg((const float4*)(pb1+j0+4));
    bv[0]=t0.x;bv[1]=t0.y;bv[2]=t0.z;bv[3]=t0.w;bv[4]=t1.x;bv[5]=t1.y;bv[6]=t1.z;bv[7]=t1.w; }
  float wv2[8];
  { float4 t0 = __ldg((const float4*)(pW2+j0)); float4 t1 = __ldg((const float4*)(pW2+j0+4));
    wv2[0]=t0.x;wv2[1]=t0.y;wv2[2]=t0.z;wv2[3]=t0.w;wv2[4]=t1.x;wv2[5]=t1.y;wv2[6]=t1.z;wv2[7]=t1.w; }

  float part[4];
  #pragma unroll
  for(int i=0;i<4;i++){
    float s = 0.f;
    #pragma unroll
    for(int j=0;j<8;j++) s = fmaf(siluf(acc[i][j] + bv[j]), wv2[j], s);
    part[i] = s;
  }
  #pragma unroll
  for(int off=8; off>=1; off>>=1){
    #pragma unroll
    for(int i=0;i<4;i++) part[i] += __shfl_xor_sync(0xffffffffu, part[i], off);
  }
  if(tx == 0){
    float pb2v = __ldg(pb2);
    #pragma unroll
    for(int i=0;i<4;i++){
      int r = r0 + i;
      float s = (part[i] + pb2v) * sInv[r];
      int row = sDstRow[r];
      atomicAdd(&g_pd[row*3+0], sRel[r*3+0]*s);
      atomicAdd(&g_pd[row*3+1], sRel[r*3+1]*s);
      atomicAdd(&g_pd[row*3+2], sRel[r*3+2]*s);
    }
  }
}

// ------------------- batch-1 delta kernel: one block per affected edge -------------------
__global__ void __launch_bounds__(128) k_delta(
    const float* __restrict__ W1r, const float* __restrict__ b1,
    const float* __restrict__ W2,  const float* __restrict__ b2,
    const float* __restrict__ pW1, const float* __restrict__ pb1,
    const float* __restrict__ pW2, const float* __restrict__ pb2,
    const int* __restrict__ esrc,  const int* __restrict__ edst, int kdeg){
  __shared__ float sm1[2][HH];
  __shared__ float sm2[2][HH];
  __shared__ float sred[8];
  int j = threadIdx.x;
  int cnt = g_acount;
  for(int idx = blockIdx.x; idx < cnt; idx += DELTA_GRID){
    int e = g_alist[idx];
    int ds = edst[e], sr = esrc[e];
    float inv = g_invdeg[kdeg*NN + ds];
    float rel[2][3], d2v[2];
    #pragma unroll
    for(int b=0;b<2;b++){
      int dr = b*NN + ds, srr = b*NN + sr;
      rel[b][0] = g_p[dr*3+0] - g_p[srr*3+0];
      rel[b][1] = g_p[dr*3+1] - g_p[srr*3+1];
      rel[b][2] = g_p[dr*3+2] - g_p[srr*3+2];
      d2v[b] = rel[b][0]*rel[b][0] + rel[b][1]*rel[b][1] + rel[b][2]*rel[b][2];
      sm1[b][j] = siluf(g_Ga[(size_t)dr*HH+j] + g_Gb[(size_t)srr*HH+j]
                        + d2v[b]*__ldg(&W1r[j]) + __ldg(&b1[j]));
    }
    __syncthreads();
    float acc0 = 0.f, acc1 = 0.f;
    #pragma unroll 4
    for(int k=0;k<HH;k++){
      float w = __ldg(&W2[k*HH+j]);
      acc0 = fmaf(sm1[0][k], w, acc0);
      acc1 = fmaf(sm1[1][k], w, acc1);
    }
    float bb = __ldg(&b2[j]);
    float m20 = siluf(acc0 + bb);
    float m21 = siluf(acc1 + bb);
    atomicAdd(&g_msum[(size_t)(NN+ds)*HH + j], (m21 - m20)*inv);
    sm2[0][j] = m20; sm2[1][j] = m21;
    __syncthreads();
    acc0 = 0.f; acc1 = 0.f;
    #pragma unroll 4
    for(int k=0;k<HH;k++){
      float w = __ldg(&pW1[k*HH+j]);
      acc0 = fmaf(sm2[0][k], w, acc0);
      acc1 = fmaf(sm2[1][k], w, acc1);
    }
    float pb = __ldg(&pb1[j]);
    float w2 = __ldg(&pW2[j]);
    float c0 = siluf(acc0 + pb) * w2;
    float c1 = siluf(acc1 + pb) * w2;
    #pragma unroll
    for(int off=16; off; off>>=1){
      c0 += __shfl_xor_sync(0xffffffffu, c0, off);
      c1 += __shfl_xor_sync(0xffffffffu, c1, off);
    }
    int wwid = j >> 5;
    if((j & 31) == 0){ sred[wwid] = c0; sred[4+wwid] = c1; }
    __syncthreads();
    if(j == 0){
      float pb2v = __ldg(pb2);
      float coef0 = sred[0]+sred[1]+sred[2]+sred[3] + pb2v;
      float coef1 = sred[4]+sred[5]+sred[6]+sred[7] + pb2v;
      atomicAdd(&g_pd[(NN+ds)*3+0], (rel[1][0]*coef1 - rel[0][0]*coef0)*inv);
      atomicAdd(&g_pd[(NN+ds)*3+1], (rel[1][1]*coef1 - rel[0][1]*coef0)*inv);
      atomicAdd(&g_pd[(NN+ds)*3+2], (rel[1][2]*coef1 - rel[0][2]*coef0)*inv);
      g_newDirty[ds] = 1;
    }
    __syncthreads();
  }
}

// ------------------- node update: h += MLP([h, m_sum]) (both batches) -------------------
__global__ void __launch_bounds__(256,2) k_update(
    const float* __restrict__ Wu1, const float* __restrict__ bu1,
    const float* __restrict__ Wu2, const float* __restrict__ bu2){
  __shared__ float sA[64*132];
  int tid = threadIdx.x;
  int base = blockIdx.x*64;
  int c4 = tid & 31, rs = tid >> 5;
  int tx = tid & 15, ty = tid >> 4;
  int r0 = ty*4, j0 = tx*8;

  float acc[4][8];
  #pragma unroll
  for(int i=0;i<4;i++)
    #pragma unroll
    for(int j=0;j<8;j++) acc[i][j]=0.f;

  #pragma unroll
  for(int it=0; it<8; it++){
    int r = it*8 + rs;
    int rg = base + r;
    float4 v = make_float4(0.f,0.f,0.f,0.f);
    if(rg < ROWS_TOT) v = __ldg((const float4*)(g_h + (size_t)rg*HH) + c4);
    *(float4*)(sA + r*132 + c4*4) = v;
  }
  __syncthreads();
  gemm_128(sA, r0, Wu1, j0, acc);
  __syncthreads();
  #pragma unroll
  for(int it=0; it<8; it++){
    int r = it*8 + rs;
    int rg = base + r;
    float4 v = make_float4(0.f,0.f,0.f,0.f);
    if(rg < ROWS_TOT) v = __ldg((const float4*)(g_msum + (size_t)rg*HH) + c4);
    *(float4*)(sA + r*132 + c4*4) = v;
  }
  __syncthreads();
  gemm_128(sA, r0, Wu1 + HH*HH, j0, acc);

  float bv[8];
  { float4 t0 = __ldg((const float4*)(bu1+j0)); float4 t1 = __ldg((const float4*)(bu1+j0+4));
    bv[0]=t0.x;bv[1]=t0.y;bv[2]=t0.z;bv[3]=t0.w;bv[4]=t1.x;bv[5]=t1.y;bv[6]=t1.z;bv[7]=t1.w; }
  float t1v[4][8];
  #pragma unroll
  for(int i=0;i<4;i++)
    #pragma unroll
    for(int j=0;j<8;j++) t1v[i][j] = siluf(acc[i][j] + bv[j]);

  __syncthreads();
  #pragma unroll
  for(int i=0;i<4;i++){
    *(float4*)(sA + (r0+i)*132 + j0)     = make_float4(t1v[i][0],t1v[i][1],t1v[i][2],t1v[i][3]);
    *(float4*)(sA + (r0+i)*132 + j0 + 4) = make_float4(t1v[i][4],t1v[i][5],t1v[i][6],t1v[i][7]);
  }
  __syncthreads();

  #pragma unroll
  for(int i=0;i<4;i++)
    #pragma unroll
    for(int j=0;j<8;j++) acc[i][j]=0.f;
  gemm_128(sA, r0, Wu2, j0, acc);

  { float4 t0 = __ldg((const float4*)(bu2+j0)); float4 t1 = __ldg((const float4*)(bu2+j0+4));
    bv[0]=t0.x;bv[1]=t0.y;bv[2]=t0.z;bv[3]=t0.w;bv[4]=t1.x;bv[5]=t1.y;bv[6]=t1.z;bv[7]=t1.w; }

  #pragma unroll
  for(int i=0;i<4;i++){
    int rg = base + r0 + i;
    if(rg < ROWS_TOT){
      float* hp = g_h + (size_t)rg*HH + j0;
      float4 h0 = *(float4*)hp;
      float4 h1 = *((float4*)hp + 1);
      h0.x += acc[i][0]+bv[0]; h0.y += acc[i][1]+bv[1];
      h0.z += acc[i][2]+bv[2]; h0.w += acc[i][3]+bv[3];
      h1.x += acc[i][4]+bv[4]; h1.y += acc[i][5]+bv[5];
      h1.z += acc[i][6]+bv[6]; h1.w += acc[i][7]+bv[7];
      *(float4*)hp = h0;
      *((float4*)hp + 1) = h1;
    }
  }
}

// ------------------- readout -------------------
__global__ void k_readout(const float* __restrict__ W1, const float* __restrict__ b1,
                          const float* __restrict__ W2, const float* __restrict__ b2,
                          const int* __restrict__ ent, float* __restrict__ out){
  __shared__ float se[HH];
  __shared__ float sred[HH];
  int j = threadIdx.x;
  for(int b=0; b<BB; b++){
    int row = b*NN + ent[b];
    se[j] = g_h[(size_t)row*HH + j];
    __syncthreads();
    float acc = b1[j];
    #pragma unroll 4
    for(int i=0;i<HH;i++) acc = fmaf(se[i], W1[i*HH+j], acc);
    sred[j] = siluf(acc) * W2[j];
    __syncthreads();
    for(int s=64; s>0; s>>=1){
      if(j<s) sred[j] += sred[j+s];
      __syncthreads();
    }
    if(j==0) out[b] = sred[0] + b2[0];
    __syncthreads();
  }
}

// ------------------- launch -------------------
extern "C" void kernel_launch(void* const* d_in, const int* in_sizes, int n_in,
                              void* d_out, int out_size){
  (void)in_sizes; (void)n_in; (void)out_size;
  const float* x     = (const float*)d_in[0];
  const float* basef = (const float*)d_in[1];
  const float* basep = (const float*)d_in[2];
  const float* Win   = (const float*)d_in[3];
  const float* b_in  = (const float*)d_in[4];
  const float* mW1   = (const float*)d_in[5];
  const float* mb1   = (const float*)d_in[6];
  const float* mW2   = (const float*)d_in[7];
  const float* mb2   = (const float*)d_in[8];
  const float* pW1   = (const float*)d_in[9];
  const float* pb1   = (const float*)d_in[10];
  const float* pW2   = (const float*)d_in[11];
  const float* pb2   = (const float*)d_in[12];
  const float* uW1   = (const float*)d_in[13];
  const float* ub1   = (const float*)d_in[14];
  const float* uW2   = (const float*)d_in[15];
  const float* ub2   = (const float*)d_in[16];
  const float* oW1   = (const float*)d_in[17];
  const float* ob1   = (const float*)d_in[18];
  const float* oW2   = (const float*)d_in[19];
  const float* ob2   = (const float*)d_in[20];
  const int*   ent   = (const int*)d_in[21];
  const int*   esrc  = (const int*)d_in[22];
  const int*   edst  = (const int*)d_in[23];
  float* out = (float*)d_out;

  k_deg_zero <<<(NBB*NN+255)/256, 256>>>();
  k_deg_count<<<(NBB*EE+255)/256, 256>>>(edst);
  k_deg_fin  <<<(NBB*NN+255)/256, 256>>>(ent);

  k_init_h <<<NN, 128>>>(basef, Win, b_in);
  k_add_dyn<<<1, 256>>>(x, Win, ent);
  k_init_p <<<(NN*3+255)/256, 256>>>(basep);

  for(int l=0; l<LL; l++){
    k_zero_layer<<<(ROWS_TOT*HH+255)/256, 256>>>();
    for(int k=0; k<NBB; k++){
      int lk = l*NBB + k;
      const float* W1lk = mW1 + (size_t)lk*257*HH;
      k_gagb<<<(ROWS_TOT+63)/64, 256>>>(W1lk);
      k_edge<<<ETILES, 256>>>(
          W1lk + 256*HH,
          mb1 + (size_t)lk*HH,
          mW2 + (size_t)lk*HH*HH,
          mb2 + (size_t)lk*HH,
          pW1 + (size_t)lk*HH*HH,
          pb1 + (size_t)lk*HH,
          pW2 + (size_t)lk*HH,
          pb2 + lk,
          esrc + (size_t)k*EE,
          edst + (size_t)k*EE,
          k);
      k_zero_cnt<<<1,1>>>();
      k_buildA<<<(EE+255)/256, 256>>>(esrc + (size_t)k*EE, edst + (size_t)k*EE);
      k_delta<<<DELTA_GRID, 128>>>(
          W1lk + 256*HH,
          mb1 + (size_t)lk*HH,
          mW2 + (size_t)lk*HH*HH,
          mb2 + (size_t)lk*HH,
          pW1 + (size_t)lk*HH*HH,
          pb1 + (size_t)lk*HH,
          pW2 + (size_t)lk*HH,
          pb2 + lk,
          esrc + (size_t)k*EE,
          edst + (size_t)k*EE,
          k);
    }
    k_merge<<<(NN*HH+255)/256, 256>>>();
    k_update<<<(ROWS_TOT+63)/64, 256>>>(
        uW1 + (size_t)l*2*HH*HH,
        ub1 + (size_t)l*HH,
        uW2 + (size_t)l*HH*HH,
        ub2 + (size_t)l*HH);
    k_padd<<<(ROWS_TOT*3+255)/256, 256>>>();
  }

  k_readout<<<1, 128>>>(oW1, ob1, oW2, ob2, ent, out);
}